// round 15
// baseline (speedup 1.0000x reference)
#include <cuda_runtime.h>
#include <cuda_fp16.h>
#include <math.h>
#include <stdint.h>

#define D_MODEL 1024
#define N_HEADS 16
#define HEAD_DIM 64
#define B_SIZE 4
#define T_LEN 2048
#define TOKENS (B_SIZE * T_LEN)   // 8192

// ---------------- scratch (device globals; allocation-free) ----------------
__device__ __half g_xh[(size_t)TOKENS * D_MODEL], g_xl[(size_t)TOKENS * D_MODEL];
__device__ __half g_wqh[(size_t)3 * D_MODEL * D_MODEL], g_wql[(size_t)3 * D_MODEL * D_MODEL];
__device__ __half g_woh[(size_t)D_MODEL * D_MODEL], g_wol[(size_t)D_MODEL * D_MODEL];
__device__ __half g_qkvh[(size_t)TOKENS * 3 * D_MODEL], g_qkvl[(size_t)TOKENS * 3 * D_MODEL];
__device__ __half g_ath[(size_t)TOKENS * D_MODEL], g_atl[(size_t)TOKENS * D_MODEL];

// ---------------------------- small helpers --------------------------------
__device__ __forceinline__ uint32_t smem_u32(const void* p) {
    uint32_t a;
    asm("{ .reg .u64 t; cvta.to.shared.u64 t, %1; cvt.u32.u64 %0, t; }"
        : "=r"(a) : "l"(p));
    return a;
}
__device__ __forceinline__ uint32_t pk_hf(__half a, __half b) {
    return (uint32_t)__half_as_ushort(a) | ((uint32_t)__half_as_ushort(b) << 16);
}
__device__ __forceinline__ void mma_f16(float* c, const uint32_t* a, const uint32_t* b) {
    asm volatile(
        "mma.sync.aligned.m16n8k16.row.col.f32.f16.f16.f32 "
        "{%0,%1,%2,%3}, {%4,%5,%6,%7}, {%8,%9}, {%0,%1,%2,%3};"
        : "+f"(c[0]), "+f"(c[1]), "+f"(c[2]), "+f"(c[3])
        : "r"(a[0]), "r"(a[1]), "r"(a[2]), "r"(a[3]), "r"(b[0]), "r"(b[1]));
}
// f16-accumulator variant: used ONLY for tiny correction passes
__device__ __forceinline__ void mma_f16acc(uint32_t* c, const uint32_t* a, const uint32_t* b) {
    asm volatile(
        "mma.sync.aligned.m16n8k16.row.col.f16.f16.f16.f16 "
        "{%0,%1}, {%2,%3,%4,%5}, {%6,%7}, {%0,%1};"
        : "+r"(c[0]), "+r"(c[1])
        : "r"(a[0]), "r"(a[1]), "r"(a[2]), "r"(a[3]), "r"(b[0]), "r"(b[1]));
}
__device__ __forceinline__ void ldmx4(uint32_t r[4], uint32_t addr) {
    asm volatile("ldmatrix.sync.aligned.m8n8.x4.shared.b16 {%0,%1,%2,%3}, [%4];"
        : "=r"(r[0]), "=r"(r[1]), "=r"(r[2]), "=r"(r[3]) : "r"(addr));
}
__device__ __forceinline__ void ldmx4t(uint32_t r[4], uint32_t addr) {
    asm volatile("ldmatrix.sync.aligned.m8n8.x4.trans.shared.b16 {%0,%1,%2,%3}, [%4];"
        : "=r"(r[0]), "=r"(r[1]), "=r"(r[2]), "=r"(r[3]) : "r"(addr));
}
__device__ __forceinline__ void cpasync16(uint32_t dst, const void* src) {
    asm volatile("cp.async.cg.shared.global [%0], [%1], 16;" :: "r"(dst), "l"(src) : "memory");
}
__device__ __forceinline__ float ex2(float x) {
    float y; asm("ex2.approx.f32 %0, %1;" : "=f"(y) : "f"(x)); return y;
}
__device__ __forceinline__ float2 up2(uint32_t v) {
    __half2 h = *reinterpret_cast<__half2*>(&v);
    return __half22float2(h);
}

// -------------------- pre-split: fp32 -> fp16 hi + lo ----------------------
__global__ __launch_bounds__(256)
void split_f16(const float* __restrict__ src, __half* __restrict__ hi,
               __half* __restrict__ lo, int n4)
{
    int i = blockIdx.x * 256 + threadIdx.x;
    if (i >= n4) return;
    float4 f = ((const float4*)src)[i];
    float v[4] = {f.x, f.y, f.z, f.w};
    __half h[4], l[4];
    #pragma unroll
    for (int j = 0; j < 4; j++) {
        h[j] = __float2half(v[j]);
        l[j] = __float2half(v[j] - __half2float(h[j]));
    }
    ((uint2*)hi)[i] = make_uint2(pk_hf(h[0], h[1]), pk_hf(h[2], h[3]));
    ((uint2*)lo)[i] = make_uint2(pk_hf(l[0], l[1]), pk_hf(l[2], l[3]));
}

// ---------------------------------------------------------------------------
// fp16 2-pass GEMM: hi-pass f32 accum, lo-pass f16 accum (tiny corrections).
// 512 threads (16 warps 4x4, warp tile 32x32), BK=64, 2-stage cp.async.
// ---------------------------------------------------------------------------
#define GSTRIDE 72
#define BUF_E (128 * GSTRIDE)      // 9216 el per buffer
#define STG_E (3 * BUF_E)          // 27648 el per stage (Ah, Al, Bh)
#define GEMM_SMEM (2 * STG_E * 2)  // 110592 bytes

__device__ __forceinline__ void stage_load(
    uint32_t sb, int s, int tid,
    const __half* __restrict__ Ah_g, const __half* __restrict__ Al_g,
    const __half* __restrict__ Bh_g,
    int brow, int bcol, int K, int k0)
{
    #pragma unroll
    for (int i = 0; i < 6; i++) {
        int c      = tid + i * 512;      // 0..3071
        int buf    = c >> 10;            // 0:Ah 1:Al 2:Bh
        int within = c & 1023;
        int row    = within >> 3;
        int ch     = within & 7;
        const __half* g = (buf == 0) ? Ah_g : (buf == 1) ? Al_g : Bh_g;
        int gr = ((buf < 2) ? brow : bcol) + row;
        const __half* src = g + (size_t)gr * K + k0 + ch * 8;
        uint32_t dst = sb + (uint32_t)((s * STG_E + buf * BUF_E + row * GSTRIDE + ch * 8) * 2);
        cpasync16(dst, src);
    }
}

template<int OM>
__global__ __launch_bounds__(512, 1)
void gemm_f16split(const __half* __restrict__ Ah_g, const __half* __restrict__ Al_g,
                   const __half* __restrict__ Bh_g,
                   const float* __restrict__ bias, float* __restrict__ C,
                   __half* __restrict__ Ch, __half* __restrict__ Cl,
                   int M, int N, int K)
{
    extern __shared__ __half sm[];
    const uint32_t sb   = smem_u32(sm);
    const int tid  = threadIdx.x;
    const int lane = tid & 31;
    const int w    = tid >> 5;
    const int wm   = w >> 2;
    const int wn   = w & 3;
    const int sub  = lane & 7;
    const int matid = lane >> 3;
    const int brow = blockIdx.y * 128;
    const int bcol = blockIdx.x * 128;

    float acc[2][4][4];
    uint32_t accL[2][4][2];          // f16x2 pairs, lo-pass accumulator
    #pragma unroll
    for (int i = 0; i < 2; i++)
        #pragma unroll
        for (int j = 0; j < 4; j++) {
            #pragma unroll
            for (int e = 0; e < 4; e++) acc[i][j][e] = 0.f;
            accL[i][j][0] = 0u; accL[i][j][1] = 0u;
        }

    const int arow = wm * 32 + ((matid & 1) << 3) + sub;
    const int acolb = ((matid >> 1) << 3);
    const int nrow = wn * 32 + ((matid >> 1) << 3) + sub;
    const int ncolb = ((matid & 1) << 3);

    const int NC = K >> 6;

    stage_load(sb, 0, tid, Ah_g, Al_g, Bh_g, brow, bcol, K, 0);
    asm volatile("cp.async.commit_group;" ::: "memory");

    for (int kc = 0; kc < NC; kc++) {
        asm volatile("cp.async.wait_group 0;" ::: "memory");
        __syncthreads();

        if (kc + 1 < NC) {
            stage_load(sb, (kc + 1) & 1, tid, Ah_g, Al_g, Bh_g,
                       brow, bcol, K, (kc + 1) * 64);
            asm volatile("cp.async.commit_group;" ::: "memory");
        }

        const int s = kc & 1;
        const uint32_t sAh = sb + (uint32_t)((s * STG_E) * 2);
        const uint32_t sAl = sAh + BUF_E * 2;
        const uint32_t sBh = sAl + BUF_E * 2;

        #pragma unroll
        for (int ks = 0; ks < 64; ks += 16) {
            uint32_t ah[2][4], al[2][4], bh[2][4];
            #pragma unroll
            for (int mt = 0; mt < 2; mt++) {
                uint32_t off = (uint32_t)(((arow + mt * 16) * GSTRIDE + ks + acolb) * 2);
                ldmx4(ah[mt], sAh + off);
                ldmx4(al[mt], sAl + off);
            }
            #pragma unroll
            for (int ng = 0; ng < 2; ng++) {
                uint32_t off = (uint32_t)(((nrow + ng * 16) * GSTRIDE + ks + ncolb) * 2);
                ldmx4(bh[ng], sBh + off);
            }
            // hi pass -> f32 accum
            #pragma unroll
            for (int mt = 0; mt < 2; mt++)
                #pragma unroll
                for (int nt = 0; nt < 4; nt++)
                    mma_f16(acc[mt][nt], ah[mt], &bh[nt >> 1][(nt & 1) * 2]);
            // lo pass (tiny corrections) -> f16 accum
            #pragma unroll
            for (int mt = 0; mt < 2; mt++)
                #pragma unroll
                for (int nt = 0; nt < 4; nt++)
                    mma_f16acc(accL[mt][nt], al[mt], &bh[nt >> 1][(nt & 1) * 2]);
        }
        __syncthreads();
    }

    const int rg = lane >> 2;
    const int ct = lane & 3;
    #pragma unroll
    for (int mt = 0; mt < 2; mt++) {
        int r0 = brow + wm * 32 + mt * 16 + rg;
        #pragma unroll
        for (int nt = 0; nt < 4; nt++) {
            int c0 = bcol + wn * 32 + nt * 8 + ct * 2;
            float b0 = bias[c0], b1 = bias[c0 + 1];
            float2 lo0 = up2(accL[mt][nt][0]);
            float2 lo1 = up2(accL[mt][nt][1]);
            float v00 = acc[mt][nt][0] + lo0.x + b0, v01 = acc[mt][nt][1] + lo0.y + b1;
            float v10 = acc[mt][nt][2] + lo1.x + b0, v11 = acc[mt][nt][3] + lo1.y + b1;
            if (OM == 0) {
                *(float2*)(C + (size_t)r0 * N + c0) = make_float2(v00, v01);
                *(float2*)(C + (size_t)(r0 + 8) * N + c0) = make_float2(v10, v11);
            } else {
                __half h00 = __float2half(v00), h01 = __float2half(v01);
                __half h10 = __float2half(v10), h11 = __float2half(v11);
                *(uint32_t*)(Ch + (size_t)r0 * N + c0) = pk_hf(h00, h01);
                *(uint32_t*)(Ch + (size_t)(r0 + 8) * N + c0) = pk_hf(h10, h11);
                *(uint32_t*)(Cl + (size_t)r0 * N + c0) = pk_hf(
                    __float2half(v00 - __half2float(h00)),
                    __float2half(v01 - __half2float(h01)));
                *(uint32_t*)(Cl + (size_t)(r0 + 8) * N + c0) = pk_hf(
                    __float2half(v10 - __half2float(h10)),
                    __float2half(v11 - __half2float(h11)));
            }
        }
    }
}

// ---------------------------------------------------------------------------
// fp16 2-pass causal flash attention; correction passes in f16 accum.
// Heaviest blocks launched first (reversed blockIdx.x).
// ---------------------------------------------------------------------------
#define FSTRIDE 72
#define KVBUF 4608
#define REGION 9216
#define QOFF 18432
#define FLASH_SMEM ((QOFF + 2 * 9216) * 2)   // 73728 bytes

__device__ __forceinline__ void load_kv(
    uint32_t sb, int region, int tid,
    const __half* __restrict__ qh, int tokbase, int h)
{
    #pragma unroll
    for (int i = 0; i < 4; i++) {
        int idx = tid + i * 256;
        int buf = idx >> 9;
        int within = idx & 511;
        int row = within >> 3, ch = within & 7;
        const __half* src = qh + (size_t)(tokbase + row) * 3072 + (buf + 1) * 1024 + h * 64 + ch * 8;
        uint32_t dst = sb + (uint32_t)((region * REGION + buf * KVBUF + row * FSTRIDE + ch * 8) * 2);
        cpasync16(dst, src);
    }
}

__global__ __launch_bounds__(256)
void flash_tc(const __half* __restrict__ qh, const __half* __restrict__ ql,
              __half* __restrict__ ath, __half* __restrict__ atl)
{
    extern __shared__ __half fs[];
    const uint32_t sb = smem_u32(fs);
    const int tid = threadIdx.x, lane = tid & 31, w = tid >> 5;
    const int b = blockIdx.z, h = blockIdx.y;
    const int q0 = (gridDim.x - 1 - blockIdx.x) * 128;   // heavy blocks first
    const int g = lane >> 2, t = lane & 3;

    #pragma unroll
    for (int i = 0; i < 8; i++) {
        int idx = tid + i * 256;
        int sp  = idx >> 10;
        int within = idx & 1023;
        int row = within >> 3, ch = within & 7;
        const __half* base = sp ? ql : qh;
        const __half* src = base + (size_t)(b * T_LEN + q0 + row) * 3072 + h * 64 + ch * 8;
        uint32_t dst = sb + (uint32_t)((QOFF + sp * 9216 + row * FSTRIDE + ch * 8) * 2);
        cpasync16(dst, src);
    }
    asm volatile("cp.async.commit_group;" ::: "memory");
    load_kv(sb, 0, tid, qh, b * T_LEN, h);
    asm volatile("cp.async.commit_group;" ::: "memory");
    asm volatile("cp.async.wait_group 0;" ::: "memory");
    __syncthreads();

    uint32_t qa_h[4][4], qa_l[4][4];
    {
        int row = w * 16 + ((lane >> 3) & 1) * 8 + (lane & 7);
        int colh = (lane >> 4) * 8;
        #pragma unroll
        for (int ks = 0; ks < 4; ks++) {
            uint32_t addr = sb + (uint32_t)((QOFF + row * FSTRIDE + ks * 16 + colh) * 2);
            ldmx4(qa_h[ks], addr);
            ldmx4(qa_l[ks], addr + 9216 * 2);
        }
    }

    const int nt_total = q0 / 64 + 2;

    float oacc[8][4];
    #pragma unroll
    for (int j = 0; j < 8; j++)
        #pragma unroll
        for (int e = 0; e < 4; e++) oacc[j][e] = 0.f;
    float m[2] = {-3.0e38f, -3.0e38f};
    float l[2] = {0.f, 0.f};

    const float SC = 0.125f * 1.44269504089f;

    for (int kt = 0; kt < nt_total; kt++) {
        const int k0 = kt * 64;
        if (kt + 1 < nt_total) {
            load_kv(sb, (kt + 1) & 1, tid, qh, b * T_LEN + (kt + 1) * 64, h);
            asm volatile("cp.async.commit_group;" ::: "memory");
            asm volatile("cp.async.wait_group 1;" ::: "memory");
        } else {
            asm volatile("cp.async.wait_group 0;" ::: "memory");
        }
        __syncthreads();

        const int rbase = q0 + w * 16 + g;
        if (k0 <= rbase + 8) {
            const uint32_t rg2 = sb + (uint32_t)(((kt & 1) * REGION) * 2);
            const uint32_t sKh = rg2, sVh = rg2 + KVBUF * 2;

            // ---- S = Q K^T: hi pass f32, lo pass f16 accum ----
            float ps[8][4];
            uint32_t psl[8][2];
            #pragma unroll
            for (int j = 0; j < 8; j++) {
                #pragma unroll
                for (int e = 0; e < 4; e++) ps[j][e] = 0.f;
                psl[j][0] = 0u; psl[j][1] = 0u;
            }

            {
                int g8 = lane >> 3;
                int krow = 8 * (g8 >> 1) + (lane & 7);
                int kcol = (g8 & 1) * 8;
                #pragma unroll
                for (int ks = 0; ks < 4; ks++) {
                    uint32_t kbh[4][4];
                    #pragma unroll
                    for (int j2 = 0; j2 < 4; j2++) {
                        uint32_t off = (uint32_t)(((16 * j2 + krow) * FSTRIDE + 16 * ks + kcol) * 2);
                        ldmx4(kbh[j2], sKh + off);
                    }
                    #pragma unroll
                    for (int j = 0; j < 8; j++)
                        mma_f16(ps[j], qa_h[ks], &kbh[j >> 1][(j & 1) * 2]);
                    #pragma unroll
                    for (int j = 0; j < 8; j++)
                        mma_f16acc(psl[j], qa_l[ks], &kbh[j >> 1][(j & 1) * 2]);
                }
            }
            // merge lo corrections
            #pragma unroll
            for (int j = 0; j < 8; j++) {
                float2 c0 = up2(psl[j][0]), c1 = up2(psl[j][1]);
                ps[j][0] += c0.x; ps[j][1] += c0.y;
                ps[j][2] += c1.x; ps[j][3] += c1.y;
            }

            // ---- scale + causal mask ----
            if (k0 + 63 > q0 + w * 16) {
                #pragma unroll
                for (int j = 0; j < 8; j++)
                    #pragma unroll
                    for (int e = 0; e < 4; e++) {
                        int col = k0 + j * 8 + t * 2 + (e & 1);
                        int row = rbase + (e >> 1) * 8;
                        ps[j][e] = (col <= row) ? ps[j][e] * SC : -1.0e30f;
                    }
            } else {
                #pragma unroll
                for (int j = 0; j < 8; j++)
                    #pragma unroll
                    for (int e = 0; e < 4; e++) ps[j][e] *= SC;
            }

            // ---- online softmax ----
            float tmax[2] = {-3.0e38f, -3.0e38f};
            #pragma unroll
            for (int j = 0; j < 8; j++) {
                tmax[0] = fmaxf(tmax[0], fmaxf(ps[j][0], ps[j][1]));
                tmax[1] = fmaxf(tmax[1], fmaxf(ps[j][2], ps[j][3]));
            }
            #pragma unroll
            for (int r = 0; r < 2; r++) {
                tmax[r] = fmaxf(tmax[r], __shfl_xor_sync(0xffffffffu, tmax[r], 1));
                tmax[r] = fmaxf(tmax[r], __shfl_xor_sync(0xffffffffu, tmax[r], 2));
            }
            float corr[2];
            #pragma unroll
            for (int r = 0; r < 2; r++) {
                float mn = fmaxf(m[r], tmax[r]);
                corr[r] = ex2(m[r] - mn);
                m[r] = mn;
            }
            float rsum[2] = {0.f, 0.f};
            #pragma unroll
            for (int j = 0; j < 8; j++)
                #pragma unroll
                for (int e = 0; e < 4; e++) {
                    float p = ex2(ps[j][e] - m[e >> 1]);
                    ps[j][e] = p;
                    rsum[e >> 1] += p;
                }
            #pragma unroll
            for (int r = 0; r < 2; r++) {
                rsum[r] += __shfl_xor_sync(0xffffffffu, rsum[r], 1);
                rsum[r] += __shfl_xor_sync(0xffffffffu, rsum[r], 2);
                l[r] = l[r] * corr[r] + rsum[r];
            }
            #pragma unroll
            for (int j = 0; j < 8; j++)
                #pragma unroll
                for (int e = 0; e < 4; e++) oacc[j][e] *= corr[e >> 1];

            // ---- O += P V: hi pass f32, lo pass f16 accum (per tile) ----
            {
                int g8 = lane >> 3;
                int vrow = (g8 & 1) * 8 + (lane & 7);
                int vcol = (g8 >> 1) * 8;
                uint32_t oaccl[8][2];
                #pragma unroll
                for (int dn = 0; dn < 8; dn++) { oaccl[dn][0] = 0u; oaccl[dn][1] = 0u; }

                #pragma unroll
                for (int ks = 0; ks < 4; ks++) {
                    uint32_t pah[4], pal[4];
                    #pragma unroll
                    for (int q2 = 0; q2 < 2; q2++) {
                        const float* pv = ps[2 * ks + q2];
                        #pragma unroll
                        for (int rh = 0; rh < 2; rh++) {
                            float p0 = pv[rh * 2 + 0], p1 = pv[rh * 2 + 1];
                            __half h0 = __float2half(p0);
                            __half h1 = __float2half(p1);
                            pah[q2 * 2 + rh] = pk_hf(h0, h1);
                            pal[q2 * 2 + rh] = pk_hf(
                                __float2half(p0 - __half2float(h0)),
                                __float2half(p1 - __half2float(h1)));
                        }
                    }
                    uint32_t vbh[4][4];
                    #pragma unroll
                    for (int j2 = 0; j2 < 4; j2++) {
                        uint32_t off = (uint32_t)(((16 * ks + vrow) * FSTRIDE + 16 * j2 + vcol) * 2);
                        ldmx4t(vbh[j2], sVh + off);
                    }
                    #pragma unroll
                    for (int dn = 0; dn < 8; dn++)
                        mma_f16(oacc[dn], pah, &vbh[dn >> 1][(dn & 1) * 2]);
                    #pragma unroll
                    for (int dn = 0; dn < 8; dn++)
                        mma_f16acc(oaccl[dn], pal, &vbh[dn >> 1][(dn & 1) * 2]);
                }
                #pragma unroll
                for (int dn = 0; dn < 8; dn++) {
                    float2 c0 = up2(oaccl[dn][0]), c1 = up2(oaccl[dn][1]);
                    oacc[dn][0] += c0.x; oacc[dn][1] += c0.y;
                    oacc[dn][2] += c1.x; oacc[dn][3] += c1.y;
                }
            }
        }
        __syncthreads();
    }

    // ---- epilogue: normalize, split fp16, store ----
    float inv[2] = {1.f / l[0], 1.f / l[1]};
    #pragma unroll
    for (int rh = 0; rh < 2; rh++) {
        int tok = b * T_LEN + q0 + w * 16 + g + rh * 8;
        #pragma unroll
        for (int j = 0; j < 8; j++) {
            int col = h * 64 + j * 8 + t * 2;
            float v0 = oacc[j][rh * 2 + 0] * inv[rh];
            float v1 = oacc[j][rh * 2 + 1] * inv[rh];
            __half h0 = __float2half(v0), h1 = __float2half(v1);
            *(uint32_t*)(ath + (size_t)tok * D_MODEL + col) = pk_hf(h0, h1);
            *(uint32_t*)(atl + (size_t)tok * D_MODEL + col) = pk_hf(
                __float2half(v0 - __half2float(h0)),
                __float2half(v1 - __half2float(h1)));
        }
    }
}

// ---------------------------------------------------------------------------
extern "C" void kernel_launch(void* const* d_in, const int* in_sizes, int n_in,
                              void* d_out, int out_size)
{
    const float *x = nullptr, *w_qkv = nullptr, *b_qkv = nullptr,
                *w_out = nullptr, *b_out = nullptr;
    for (int i = 0; i < n_in; i++) {
        switch (in_sizes[i]) {
            case 8388608: x     = (const float*)d_in[i]; break;
            case 3145728: w_qkv = (const float*)d_in[i]; break;
            case 3072:    b_qkv = (const float*)d_in[i]; break;
            case 1048576: w_out = (const float*)d_in[i]; break;
            case 1024:    b_out = (const float*)d_in[i]; break;
            default: break;
        }
    }
    float* out = (float*)d_out;

    __half *xh, *xl, *wqh, *wql, *woh, *wol, *qkvh, *qkvl, *ath, *atl;
    cudaGetSymbolAddress((void**)&xh, g_xh);   cudaGetSymbolAddress((void**)&xl, g_xl);
    cudaGetSymbolAddress((void**)&wqh, g_wqh); cudaGetSymbolAddress((void**)&wql, g_wql);
    cudaGetSymbolAddress((void**)&woh, g_woh); cudaGetSymbolAddress((void**)&wol, g_wol);
    cudaGetSymbolAddress((void**)&qkvh, g_qkvh); cudaGetSymbolAddress((void**)&qkvl, g_qkvl);
    cudaGetSymbolAddress((void**)&ath, g_ath); cudaGetSymbolAddress((void**)&atl, g_atl);

    cudaFuncSetAttribute(gemm_f16split<0>, cudaFuncAttributeMaxDynamicSharedMemorySize, GEMM_SMEM);
    cudaFuncSetAttribute(gemm_f16split<1>, cudaFuncAttributeMaxDynamicSharedMemorySize, GEMM_SMEM);
    cudaFuncSetAttribute(flash_tc, cudaFuncAttributeMaxDynamicSharedMemorySize, FLASH_SMEM);

    // 0) pre-split inputs
    int n4x = TOKENS * D_MODEL / 4;
    split_f16<<<(n4x + 255) / 256, 256>>>(x, xh, xl, n4x);
    int n4q = 3 * D_MODEL * D_MODEL / 4;
    split_f16<<<(n4q + 255) / 256, 256>>>(w_qkv, wqh, wql, n4q);
    int n4o = D_MODEL * D_MODEL / 4;
    split_f16<<<(n4o + 255) / 256, 256>>>(w_out, woh, wol, n4o);

    // 1) QKV projection -> split fp16 qkv
    gemm_f16split<1><<<dim3(3 * D_MODEL / 128, TOKENS / 128), 512, GEMM_SMEM>>>(
        xh, xl, wqh, b_qkv, nullptr, qkvh, qkvl, TOKENS, 3 * D_MODEL, D_MODEL);

    // 2) TC causal flash attention -> split fp16 attn
    flash_tc<<<dim3(T_LEN / 128, N_HEADS, B_SIZE), 256, FLASH_SMEM>>>(qkvh, qkvl, ath, atl);

    // 3) Output projection -> fp32 d_out
    gemm_f16split<0><<<dim3(D_MODEL / 128, TOKENS / 128), 512, GEMM_SMEM>>>(
        ath, atl, woh, b_out, out, nullptr, nullptr, TOKENS, D_MODEL, D_MODEL);
}

// round 16
// speedup vs baseline: 1.3380x; 1.3380x over previous
#include <cuda_runtime.h>
#include <cuda_fp16.h>
#include <math.h>
#include <stdint.h>

#define D_MODEL 1024
#define N_HEADS 16
#define HEAD_DIM 64
#define B_SIZE 4
#define T_LEN 2048
#define TOKENS (B_SIZE * T_LEN)   // 8192

// ---------------- scratch (device globals; allocation-free) ----------------
__device__ __half g_xh[(size_t)TOKENS * D_MODEL];
__device__ __half g_wqh[(size_t)3 * D_MODEL * D_MODEL];
__device__ __half g_woh[(size_t)D_MODEL * D_MODEL];
__device__ __half g_qkvh[(size_t)TOKENS * 3 * D_MODEL], g_qkvl[(size_t)TOKENS * 3 * D_MODEL];
__device__ __half g_ath[(size_t)TOKENS * D_MODEL];

// ---------------------------- small helpers --------------------------------
__device__ __forceinline__ uint32_t smem_u32(const void* p) {
    uint32_t a;
    asm("{ .reg .u64 t; cvta.to.shared.u64 t, %1; cvt.u32.u64 %0, t; }"
        : "=r"(a) : "l"(p));
    return a;
}
__device__ __forceinline__ uint32_t pk_hf(__half a, __half b) {
    return (uint32_t)__half_as_ushort(a) | ((uint32_t)__half_as_ushort(b) << 16);
}
__device__ __forceinline__ void mma_f16(float* c, const uint32_t* a, const uint32_t* b) {
    asm volatile(
        "mma.sync.aligned.m16n8k16.row.col.f32.f16.f16.f32 "
        "{%0,%1,%2,%3}, {%4,%5,%6,%7}, {%8,%9}, {%0,%1,%2,%3};"
        : "+f"(c[0]), "+f"(c[1]), "+f"(c[2]), "+f"(c[3])
        : "r"(a[0]), "r"(a[1]), "r"(a[2]), "r"(a[3]), "r"(b[0]), "r"(b[1]));
}
__device__ __forceinline__ void ldmx4(uint32_t r[4], uint32_t addr) {
    asm volatile("ldmatrix.sync.aligned.m8n8.x4.shared.b16 {%0,%1,%2,%3}, [%4];"
        : "=r"(r[0]), "=r"(r[1]), "=r"(r[2]), "=r"(r[3]) : "r"(addr));
}
__device__ __forceinline__ void ldmx4t(uint32_t r[4], uint32_t addr) {
    asm volatile("ldmatrix.sync.aligned.m8n8.x4.trans.shared.b16 {%0,%1,%2,%3}, [%4];"
        : "=r"(r[0]), "=r"(r[1]), "=r"(r[2]), "=r"(r[3]) : "r"(addr));
}
__device__ __forceinline__ void cpasync16(uint32_t dst, const void* src) {
    asm volatile("cp.async.cg.shared.global [%0], [%1], 16;" :: "r"(dst), "l"(src) : "memory");
}
__device__ __forceinline__ float ex2(float x) {
    float y; asm("ex2.approx.f32 %0, %1;" : "=f"(y) : "f"(x)); return y;
}

// -------------------- pre-convert: fp32 -> fp16 (hi only) ------------------
__global__ __launch_bounds__(256)
void cvt_f16(const float* __restrict__ src, __half* __restrict__ hi, int n4)
{
    int i = blockIdx.x * 256 + threadIdx.x;
    if (i >= n4) return;
    float4 f = ((const float4*)src)[i];
    ((uint2*)hi)[i] = make_uint2(
        pk_hf(__float2half(f.x), __float2half(f.y)),
        pk_hf(__float2half(f.z), __float2half(f.w)));
}

// ---------------------------------------------------------------------------
// fp16 single-pass GEMM: C[M,N] = A@W^T + bias (A, W both fp16-rounded).
// 512 threads (16 warps 4x4, warp tile 32x32), BK=64, 2-stage cp.async,
// stride-72 smem rows. OM=0: fp32 out; OM=1: fp16 hi/lo out.
// ---------------------------------------------------------------------------
#define GSTRIDE 72
#define BUF_E (128 * GSTRIDE)      // 9216 el per buffer
#define STG_E (2 * BUF_E)          // 18432 el per stage (Ah, Bh)
#define GEMM_SMEM (2 * STG_E * 2)  // 73728 bytes

__device__ __forceinline__ void stage_load(
    uint32_t sb, int s, int tid,
    const __half* __restrict__ Ah_g, const __half* __restrict__ Bh_g,
    int brow, int bcol, int K, int k0)
{
    // 2 buffers * 128 rows * 8 chunks = 2048 16B chunks; 512 thr * 4 iters
    #pragma unroll
    for (int i = 0; i < 4; i++) {
        int c      = tid + i * 512;      // 0..2047
        int buf    = c >> 10;            // 0:Ah 1:Bh
        int within = c & 1023;
        int row    = within >> 3;
        int ch     = within & 7;
        const __half* g = (buf == 0) ? Ah_g : Bh_g;
        int gr = ((buf == 0) ? brow : bcol) + row;
        const __half* src = g + (size_t)gr * K + k0 + ch * 8;
        uint32_t dst = sb + (uint32_t)((s * STG_E + buf * BUF_E + row * GSTRIDE + ch * 8) * 2);
        cpasync16(dst, src);
    }
}

template<int OM>
__global__ __launch_bounds__(512, 1)
void gemm_f16(const __half* __restrict__ Ah_g, const __half* __restrict__ Bh_g,
              const float* __restrict__ bias, float* __restrict__ C,
              __half* __restrict__ Ch, __half* __restrict__ Cl,
              int M, int N, int K)
{
    extern __shared__ __half sm[];
    const uint32_t sb   = smem_u32(sm);
    const int tid  = threadIdx.x;
    const int lane = tid & 31;
    const int w    = tid >> 5;
    const int wm   = w >> 2;
    const int wn   = w & 3;
    const int sub  = lane & 7;
    const int matid = lane >> 3;
    const int brow = blockIdx.y * 128;
    const int bcol = blockIdx.x * 128;

    float acc[2][4][4];
    #pragma unroll
    for (int i = 0; i < 2; i++)
        #pragma unroll
        for (int j = 0; j < 4; j++)
            #pragma unroll
            for (int e = 0; e < 4; e++) acc[i][j][e] = 0.f;

    const int arow = wm * 32 + ((matid & 1) << 3) + sub;
    const int acolb = ((matid >> 1) << 3);
    const int nrow = wn * 32 + ((matid >> 1) << 3) + sub;
    const int ncolb = ((matid & 1) << 3);

    const int NC = K >> 6;

    stage_load(sb, 0, tid, Ah_g, Bh_g, brow, bcol, K, 0);
    asm volatile("cp.async.commit_group;" ::: "memory");

    for (int kc = 0; kc < NC; kc++) {
        asm volatile("cp.async.wait_group 0;" ::: "memory");
        __syncthreads();

        if (kc + 1 < NC) {
            stage_load(sb, (kc + 1) & 1, tid, Ah_g, Bh_g,
                       brow, bcol, K, (kc + 1) * 64);
            asm volatile("cp.async.commit_group;" ::: "memory");
        }

        const int s = kc & 1;
        const uint32_t sAh = sb + (uint32_t)((s * STG_E) * 2);
        const uint32_t sBh = sAh + BUF_E * 2;

        #pragma unroll
        for (int ks = 0; ks < 64; ks += 16) {
            uint32_t ah[2][4], bh[2][4];
            #pragma unroll
            for (int mt = 0; mt < 2; mt++) {
                uint32_t off = (uint32_t)(((arow + mt * 16) * GSTRIDE + ks + acolb) * 2);
                ldmx4(ah[mt], sAh + off);
            }
            #pragma unroll
            for (int ng = 0; ng < 2; ng++) {
                uint32_t off = (uint32_t)(((nrow + ng * 16) * GSTRIDE + ks + ncolb) * 2);
                ldmx4(bh[ng], sBh + off);
            }
            #pragma unroll
            for (int mt = 0; mt < 2; mt++)
                #pragma unroll
                for (int nt = 0; nt < 4; nt++)
                    mma_f16(acc[mt][nt], ah[mt], &bh[nt >> 1][(nt & 1) * 2]);
        }
        __syncthreads();
    }

    const int rg = lane >> 2;
    const int ct = lane & 3;
    #pragma unroll
    for (int mt = 0; mt < 2; mt++) {
        int r0 = brow + wm * 32 + mt * 16 + rg;
        #pragma unroll
        for (int nt = 0; nt < 4; nt++) {
            int c0 = bcol + wn * 32 + nt * 8 + ct * 2;
            float b0 = bias[c0], b1 = bias[c0 + 1];
            float v00 = acc[mt][nt][0] + b0, v01 = acc[mt][nt][1] + b1;
            float v10 = acc[mt][nt][2] + b0, v11 = acc[mt][nt][3] + b1;
            if (OM == 0) {
                *(float2*)(C + (size_t)r0 * N + c0) = make_float2(v00, v01);
                *(float2*)(C + (size_t)(r0 + 8) * N + c0) = make_float2(v10, v11);
            } else {
                __half h00 = __float2half(v00), h01 = __float2half(v01);
                __half h10 = __float2half(v10), h11 = __float2half(v11);
                *(uint32_t*)(Ch + (size_t)r0 * N + c0) = pk_hf(h00, h01);
                *(uint32_t*)(Ch + (size_t)(r0 + 8) * N + c0) = pk_hf(h10, h11);
                *(uint32_t*)(Cl + (size_t)r0 * N + c0) = pk_hf(
                    __float2half(v00 - __half2float(h00)),
                    __float2half(v01 - __half2float(h01)));
                *(uint32_t*)(Cl + (size_t)(r0 + 8) * N + c0) = pk_hf(
                    __float2half(v10 - __half2float(h10)),
                    __float2half(v11 - __half2float(h11)));
            }
        }
    }
}

// ---------------------------------------------------------------------------
// fp16 2-pass causal flash attention. Q/P exact (hi+lo), K/V fp16 hi only.
// Block: 128 q rows x one (b,h). 256 thr, 8 warps x 16 rows.
// Heaviest causal blocks launched first (reversed blockIdx.x).
// ---------------------------------------------------------------------------
#define FSTRIDE 72
#define KVBUF 4608            // 64*72 el per buffer
#define REGION 9216           // per stage: Kh + Vh
#define QOFF 18432            // Q hi/lo planes after 2 KV stages
#define FLASH_SMEM ((QOFF + 2 * 9216) * 2)   // 73728 bytes

__device__ __forceinline__ void load_kv(
    uint32_t sb, int region, int tid,
    const __half* __restrict__ qh, int tokbase, int h)
{
    #pragma unroll
    for (int i = 0; i < 4; i++) {
        int idx = tid + i * 256;          // 0..1023
        int buf = idx >> 9;               // 0:Kh 1:Vh
        int within = idx & 511;
        int row = within >> 3, ch = within & 7;
        const __half* src = qh + (size_t)(tokbase + row) * 3072 + (buf + 1) * 1024 + h * 64 + ch * 8;
        uint32_t dst = sb + (uint32_t)((region * REGION + buf * KVBUF + row * FSTRIDE + ch * 8) * 2);
        cpasync16(dst, src);
    }
}

__global__ __launch_bounds__(256)
void flash_tc(const __half* __restrict__ qh, const __half* __restrict__ ql,
              __half* __restrict__ ath)
{
    extern __shared__ __half fs[];
    const uint32_t sb = smem_u32(fs);
    const int tid = threadIdx.x, lane = tid & 31, w = tid >> 5;
    const int b = blockIdx.z, h = blockIdx.y;
    const int q0 = (gridDim.x - 1 - blockIdx.x) * 128;   // heavy blocks first
    const int g = lane >> 2, t = lane & 3;

    // ---- stage Q hi/lo + KV tile 0 ----
    #pragma unroll
    for (int i = 0; i < 8; i++) {
        int idx = tid + i * 256;
        int sp  = idx >> 10;
        int within = idx & 1023;
        int row = within >> 3, ch = within & 7;
        const __half* base = sp ? ql : qh;
        const __half* src = base + (size_t)(b * T_LEN + q0 + row) * 3072 + h * 64 + ch * 8;
        uint32_t dst = sb + (uint32_t)((QOFF + sp * 9216 + row * FSTRIDE + ch * 8) * 2);
        cpasync16(dst, src);
    }
    asm volatile("cp.async.commit_group;" ::: "memory");
    load_kv(sb, 0, tid, qh, b * T_LEN, h);
    asm volatile("cp.async.commit_group;" ::: "memory");
    asm volatile("cp.async.wait_group 0;" ::: "memory");
    __syncthreads();

    uint32_t qa_h[4][4], qa_l[4][4];
    {
        int row = w * 16 + ((lane >> 3) & 1) * 8 + (lane & 7);
        int colh = (lane >> 4) * 8;
        #pragma unroll
        for (int ks = 0; ks < 4; ks++) {
            uint32_t addr = sb + (uint32_t)((QOFF + row * FSTRIDE + ks * 16 + colh) * 2);
            ldmx4(qa_h[ks], addr);
            ldmx4(qa_l[ks], addr + 9216 * 2);
        }
    }

    const int nt_total = q0 / 64 + 2;

    float oacc[8][4];
    #pragma unroll
    for (int j = 0; j < 8; j++)
        #pragma unroll
        for (int e = 0; e < 4; e++) oacc[j][e] = 0.f;
    float m[2] = {-3.0e38f, -3.0e38f};
    float l[2] = {0.f, 0.f};

    const float SC = 0.125f * 1.44269504089f;

    for (int kt = 0; kt < nt_total; kt++) {
        const int k0 = kt * 64;
        if (kt + 1 < nt_total) {
            load_kv(sb, (kt + 1) & 1, tid, qh, b * T_LEN + (kt + 1) * 64, h);
            asm volatile("cp.async.commit_group;" ::: "memory");
            asm volatile("cp.async.wait_group 1;" ::: "memory");
        } else {
            asm volatile("cp.async.wait_group 0;" ::: "memory");
        }
        __syncthreads();

        const int rbase = q0 + w * 16 + g;
        if (k0 <= rbase + 8) {
            const uint32_t rg2 = sb + (uint32_t)(((kt & 1) * REGION) * 2);
            const uint32_t sKh = rg2, sVh = rg2 + KVBUF * 2;

            // ---- S = Q K^T (2-pass: Qh*Kh + Ql*Kh, both f32 accum) ----
            float ps[8][4];
            #pragma unroll
            for (int j = 0; j < 8; j++)
                #pragma unroll
                for (int e = 0; e < 4; e++) ps[j][e] = 0.f;

            {
                int g8 = lane >> 3;
                int krow = 8 * (g8 >> 1) + (lane & 7);
                int kcol = (g8 & 1) * 8;
                #pragma unroll
                for (int ks = 0; ks < 4; ks++) {
                    uint32_t kbh[4][4];
                    #pragma unroll
                    for (int j2 = 0; j2 < 4; j2++) {
                        uint32_t off = (uint32_t)(((16 * j2 + krow) * FSTRIDE + 16 * ks + kcol) * 2);
                        ldmx4(kbh[j2], sKh + off);
                    }
                    #pragma unroll
                    for (int sp = 0; sp < 2; sp++) {
                        const uint32_t* qa = sp ? qa_l[ks] : qa_h[ks];
                        #pragma unroll
                        for (int j = 0; j < 8; j++)
                            mma_f16(ps[j], qa, &kbh[j >> 1][(j & 1) * 2]);
                    }
                }
            }

            // ---- scale + causal mask ----
            if (k0 + 63 > q0 + w * 16) {
                #pragma unroll
                for (int j = 0; j < 8; j++)
                    #pragma unroll
                    for (int e = 0; e < 4; e++) {
                        int col = k0 + j * 8 + t * 2 + (e & 1);
                        int row = rbase + (e >> 1) * 8;
                        ps[j][e] = (col <= row) ? ps[j][e] * SC : -1.0e30f;
                    }
            } else {
                #pragma unroll
                for (int j = 0; j < 8; j++)
                    #pragma unroll
                    for (int e = 0; e < 4; e++) ps[j][e] *= SC;
            }

            // ---- online softmax ----
            float tmax[2] = {-3.0e38f, -3.0e38f};
            #pragma unroll
            for (int j = 0; j < 8; j++) {
                tmax[0] = fmaxf(tmax[0], fmaxf(ps[j][0], ps[j][1]));
                tmax[1] = fmaxf(tmax[1], fmaxf(ps[j][2], ps[j][3]));
            }
            #pragma unroll
            for (int r = 0; r < 2; r++) {
                tmax[r] = fmaxf(tmax[r], __shfl_xor_sync(0xffffffffu, tmax[r], 1));
                tmax[r] = fmaxf(tmax[r], __shfl_xor_sync(0xffffffffu, tmax[r], 2));
            }
            float corr[2];
            #pragma unroll
            for (int r = 0; r < 2; r++) {
                float mn = fmaxf(m[r], tmax[r]);
                corr[r] = ex2(m[r] - mn);
                m[r] = mn;
            }
            float rsum[2] = {0.f, 0.f};
            #pragma unroll
            for (int j = 0; j < 8; j++)
                #pragma unroll
                for (int e = 0; e < 4; e++) {
                    float p = ex2(ps[j][e] - m[e >> 1]);
                    ps[j][e] = p;
                    rsum[e >> 1] += p;
                }
            #pragma unroll
            for (int r = 0; r < 2; r++) {
                rsum[r] += __shfl_xor_sync(0xffffffffu, rsum[r], 1);
                rsum[r] += __shfl_xor_sync(0xffffffffu, rsum[r], 2);
                l[r] = l[r] * corr[r] + rsum[r];
            }
            #pragma unroll
            for (int j = 0; j < 8; j++)
                #pragma unroll
                for (int e = 0; e < 4; e++) oacc[j][e] *= corr[e >> 1];

            // ---- O += P V (2-pass: Ph*Vh + Pl*Vh, both f32 accum) ----
            {
                int g8 = lane >> 3;
                int vrow = (g8 & 1) * 8 + (lane & 7);
                int vcol = (g8 >> 1) * 8;
                #pragma unroll
                for (int ks = 0; ks < 4; ks++) {
                    uint32_t pah[4], pal[4];
                    #pragma unroll
                    for (int q2 = 0; q2 < 2; q2++) {
                        const float* pv = ps[2 * ks + q2];
                        #pragma unroll
                        for (int rh = 0; rh < 2; rh++) {
                            float p0 = pv[rh * 2 + 0], p1 = pv[rh * 2 + 1];
                            __half h0 = __float2half(p0);
                            __half h1 = __float2half(p1);
                            pah[q2 * 2 + rh] = pk_hf(h0, h1);
                            pal[q2 * 2 + rh] = pk_hf(
                                __float2half(p0 - __half2float(h0)),
                                __float2half(p1 - __half2float(h1)));
                        }
                    }
                    uint32_t vbh[4][4];
                    #pragma unroll
                    for (int j2 = 0; j2 < 4; j2++) {
                        uint32_t off = (uint32_t)(((16 * ks + vrow) * FSTRIDE + 16 * j2 + vcol) * 2);
                        ldmx4t(vbh[j2], sVh + off);
                    }
                    #pragma unroll
                    for (int sp = 0; sp < 2; sp++) {
                        const uint32_t* pa = sp ? pal : pah;
                        #pragma unroll
                        for (int dn = 0; dn < 8; dn++)
                            mma_f16(oacc[dn], pa, &vbh[dn >> 1][(dn & 1) * 2]);
                    }
                }
            }
        }
        __syncthreads();
    }

    // ---- epilogue: normalize, fp16, store (out-proj is 1-pass: hi only) ----
    float inv[2] = {1.f / l[0], 1.f / l[1]};
    #pragma unroll
    for (int rh = 0; rh < 2; rh++) {
        int tok = b * T_LEN + q0 + w * 16 + g + rh * 8;
        #pragma unroll
        for (int j = 0; j < 8; j++) {
            int col = h * 64 + j * 8 + t * 2;
            float v0 = oacc[j][rh * 2 + 0] * inv[rh];
            float v1 = oacc[j][rh * 2 + 1] * inv[rh];
            *(uint32_t*)(ath + (size_t)tok * D_MODEL + col) =
                pk_hf(__float2half(v0), __float2half(v1));
        }
    }
}

// ---------------------------------------------------------------------------
extern "C" void kernel_launch(void* const* d_in, const int* in_sizes, int n_in,
                              void* d_out, int out_size)
{
    const float *x = nullptr, *w_qkv = nullptr, *b_qkv = nullptr,
                *w_out = nullptr, *b_out = nullptr;
    for (int i = 0; i < n_in; i++) {
        switch (in_sizes[i]) {
            case 8388608: x     = (const float*)d_in[i]; break;
            case 3145728: w_qkv = (const float*)d_in[i]; break;
            case 3072:    b_qkv = (const float*)d_in[i]; break;
            case 1048576: w_out = (const float*)d_in[i]; break;
            case 1024:    b_out = (const float*)d_in[i]; break;
            default: break;
        }
    }
    float* out = (float*)d_out;

    __half *xh, *wqh, *woh, *qkvh, *qkvl, *ath;
    cudaGetSymbolAddress((void**)&xh, g_xh);
    cudaGetSymbolAddress((void**)&wqh, g_wqh);
    cudaGetSymbolAddress((void**)&woh, g_woh);
    cudaGetSymbolAddress((void**)&qkvh, g_qkvh); cudaGetSymbolAddress((void**)&qkvl, g_qkvl);
    cudaGetSymbolAddress((void**)&ath, g_ath);

    cudaFuncSetAttribute(gemm_f16<0>, cudaFuncAttributeMaxDynamicSharedMemorySize, GEMM_SMEM);
    cudaFuncSetAttribute(gemm_f16<1>, cudaFuncAttributeMaxDynamicSharedMemorySize, GEMM_SMEM);
    cudaFuncSetAttribute(flash_tc, cudaFuncAttributeMaxDynamicSharedMemorySize, FLASH_SMEM);

    // 0) pre-convert inputs to fp16 (hi only; corrections live in qkv split)
    int n4x = TOKENS * D_MODEL / 4;
    cvt_f16<<<(n4x + 255) / 256, 256>>>(x, xh, n4x);
    int n4q = 3 * D_MODEL * D_MODEL / 4;
    cvt_f16<<<(n4q + 255) / 256, 256>>>(w_qkv, wqh, n4q);
    int n4o = D_MODEL * D_MODEL / 4;
    cvt_f16<<<(n4o + 255) / 256, 256>>>(w_out, woh, n4o);

    // 1) QKV projection (1-pass fp16) -> split fp16 qkv (hi+lo for flash Q/corrections)
    gemm_f16<1><<<dim3(3 * D_MODEL / 128, TOKENS / 128), 512, GEMM_SMEM>>>(
        xh, wqh, b_qkv, nullptr, qkvh, qkvl, TOKENS, 3 * D_MODEL, D_MODEL);

    // 2) TC causal flash attention (2-pass) -> fp16 attn (hi only)
    flash_tc<<<dim3(T_LEN / 128, N_HEADS, B_SIZE), 256, FLASH_SMEM>>>(qkvh, qkvl, ath);

    // 3) Output projection (1-pass fp16) -> fp32 d_out
    gemm_f16<0><<<dim3(D_MODEL / 128, TOKENS / 128), 512, GEMM_SMEM>>>(
        ath, woh, b_out, out, nullptr, nullptr, TOKENS, D_MODEL, D_MODEL);
}